// round 1
// baseline (speedup 1.0000x reference)
#include <cuda_runtime.h>
#include <cuda_bf16.h>

// Problem constants (from reference)
#define NROWS 262144
#define DD 128
#define HH 16
#define EE 21

#define M_TILE 128
#define MAIN_THREADS 128
#define MAX_TILES ((NROWS / M_TILE) + EE + 1)   // 2048 + 22

// Scratch (device globals; no allocation allowed)
__device__ int g_counts[EE];
__device__ int g_cursor[EE];
__device__ int g_offsets[EE + 1];
__device__ int g_tileOff[EE + 1];
__device__ int g_numTiles;
__device__ int g_perm[NROWS];

// ---------------- K0: zero counters ----------------
__global__ void k_zero() {
    int t = threadIdx.x;
    if (t < EE) g_counts[t] = 0;
}

// ---------------- K1: histogram of sid ----------------
__global__ void k_hist(const int* __restrict__ sid) {
    __shared__ int sh[EE];
    int tid = threadIdx.x;
    if (tid < EE) sh[tid] = 0;
    __syncthreads();
    int idx = blockIdx.x * blockDim.x + tid;
    if (idx < NROWS) atomicAdd(&sh[sid[idx]], 1);
    __syncthreads();
    if (tid < EE) atomicAdd(&g_counts[tid], sh[tid]);
}

// ---------------- K2: exclusive scan + tile offsets (tiny, 1 thread) -------
__global__ void k_scan() {
    int offs = 0, T = 0;
    for (int e = 0; e < EE; e++) {
        g_offsets[e] = offs;
        g_cursor[e] = offs;
        g_tileOff[e] = T;
        int c = g_counts[e];
        T += (c + M_TILE - 1) / M_TILE;
        offs += c;
    }
    g_offsets[EE] = offs;
    g_tileOff[EE] = T;
    g_numTiles = T;
}

// ---------------- K3: scatter rows into expert-grouped order ----------------
__global__ void k_scatter(const int* __restrict__ sid) {
    __shared__ int sHist[EE];
    __shared__ int sBase[EE];
    int tid = threadIdx.x;
    if (tid < EE) sHist[tid] = 0;
    __syncthreads();
    int gid = blockIdx.x * blockDim.x + tid;
    int e = -1, myIdx = 0;
    if (gid < NROWS) {
        e = sid[gid];
        myIdx = atomicAdd(&sHist[e], 1);
    }
    __syncthreads();
    if (tid < EE) sBase[tid] = atomicAdd(&g_cursor[tid], sHist[tid]);
    __syncthreads();
    if (gid < NROWS) g_perm[sBase[e] + myIdx] = gid;
}

// ---------------- K4: grouped expert MLP ----------------
// One CTA = one (expert, 128-row tile). Weights W1^T in smem (broadcast LDS),
// x tile staged in smem with stride 132 floats (conflict-free LDS.128).
#define XS_STRIDE 132
#define SMEM_FLOATS (M_TILE * XS_STRIDE + DD * HH + HH + HH + 1)
#define SMEM_BYTES (SMEM_FLOATS * 4 + M_TILE * 4)

__global__ __launch_bounds__(MAIN_THREADS, 2)
void k_main(const float* __restrict__ x,
            const float* __restrict__ W1,
            const float* __restrict__ b1,
            const float* __restrict__ W2,
            const float* __restrict__ b2,
            float* __restrict__ out)
{
    extern __shared__ float smem[];
    float* xs  = smem;                       // [128][132]
    float* wT  = smem + M_TILE * XS_STRIDE;  // [16][128] = W1^T for this expert
    float* sb1 = wT + DD * HH;               // [16]
    float* sw2 = sb1 + HH;                   // [16]
    float* sb2 = sw2 + HH;                   // [1]
    int*  sRow = (int*)(sb2 + 1);            // [128]

    int t = blockIdx.x;
    if (t >= g_numTiles) return;

    // Find our expert via the (small, cached) tile offset table.
    int e = 0;
    #pragma unroll
    for (int i = 1; i < EE; i++)
        if (t >= g_tileOff[i]) e = i;
    int ti       = t - g_tileOff[e];
    int rowStart = g_offsets[e] + ti * M_TILE;
    int valid    = g_counts[e] - ti * M_TILE;
    if (valid > M_TILE) valid = M_TILE;

    int tid = threadIdx.x;

    // Stage row indices + expert weights/biases.
    if (tid < valid) sRow[tid] = g_perm[rowStart + tid];
    const float* W1e = W1 + (size_t)e * (DD * HH);
    for (int i = tid; i < DD * HH; i += MAIN_THREADS) {
        int k = i >> 4, j = i & 15;
        wT[j * DD + k] = W1e[i];             // transpose: wT[j][k]
    }
    if (tid < HH) {
        sb1[tid] = b1[e * HH + tid];
        sw2[tid] = W2[e * HH + tid];
    }
    if (tid == 0) sb2[0] = b2[e];
    __syncthreads();

    // Stage x rows: one warp reads one full 512B row per instruction (coalesced).
    int total = valid * 32;                  // 32 float4 segments per row
    for (int i = tid; i < total; i += MAIN_THREADS) {
        int r = i >> 5, s = i & 31;
        float4 v = *((const float4*)(x + (size_t)sRow[r] * DD) + s);
        *(float4*)(xs + r * XS_STRIDE + s * 4) = v;
    }
    __syncthreads();

    if (tid < valid) {
        float acc[HH];
        #pragma unroll
        for (int j = 0; j < HH; j++) acc[j] = 0.0f;

        const float* xrow = xs + tid * XS_STRIDE;
        for (int k4 = 0; k4 < DD / 4; k4++) {
            float4 xv = *(const float4*)(xrow + k4 * 4);
            #pragma unroll
            for (int j = 0; j < HH; j++) {
                float4 wv = *(const float4*)(wT + j * DD + k4 * 4); // warp-uniform broadcast
                acc[j] += xv.x * wv.x;
                acc[j] += xv.y * wv.y;
                acc[j] += xv.z * wv.z;
                acc[j] += xv.w * wv.w;
            }
        }

        float y = sb2[0];
        #pragma unroll
        for (int j = 0; j < HH; j++) {
            float h = fmaxf(acc[j] + sb1[j], 0.0f);
            y = fmaf(h, sw2[j], y);
        }
        y = fmaxf(y, 0.0f);
        out[sRow[tid]] = y;
    }
}

extern "C" void kernel_launch(void* const* d_in, const int* in_sizes, int n_in,
                              void* d_out, int out_size)
{
    const float* x   = (const float*)d_in[0];
    const int*   sid = (const int*)d_in[1];
    const float* W1  = (const float*)d_in[2];
    const float* b1  = (const float*)d_in[3];
    const float* W2  = (const float*)d_in[4];
    const float* b2  = (const float*)d_in[5];
    float* out = (float*)d_out;

    static bool attr_set = false;
    if (!attr_set) {
        cudaFuncSetAttribute(k_main, cudaFuncAttributeMaxDynamicSharedMemorySize, SMEM_BYTES);
        attr_set = true;
    }

    k_zero<<<1, 32>>>();
    k_hist<<<NROWS / 1024, 1024>>>(sid);
    k_scan<<<1, 1>>>();
    k_scatter<<<NROWS / 512, 512>>>(sid);
    k_main<<<MAX_TILES, MAIN_THREADS, SMEM_BYTES>>>(x, W1, b1, W2, b2, out);
}

// round 2
// speedup vs baseline: 2.3865x; 2.3865x over previous
#include <cuda_runtime.h>
#include <cuda_bf16.h>
#include <cstdint>

// Problem constants
#define NROWS 262144
#define DD 128
#define HH 16
#define EE 21

#define M_TILE 128
#define MAIN_THREADS 128
#define MAX_TILES ((NROWS / M_TILE) + EE + 1)

// Scratch (device globals; allocation forbidden)
__device__ int g_counts[EE];
__device__ int g_cursor[EE];
__device__ int g_offsets[EE + 1];
__device__ int g_tileOff[EE + 1];
__device__ int g_numTiles;
__device__ int g_perm[NROWS];

// ---------------- K0: zero counters ----------------
__global__ void k_zero() {
    int t = threadIdx.x;
    if (t < EE) g_counts[t] = 0;
}

// ---------------- K1: histogram of sid ----------------
__global__ void k_hist(const int* __restrict__ sid) {
    __shared__ int sh[EE];
    int tid = threadIdx.x;
    if (tid < EE) sh[tid] = 0;
    __syncthreads();
    int idx = blockIdx.x * blockDim.x + tid;
    if (idx < NROWS) atomicAdd(&sh[sid[idx]], 1);
    __syncthreads();
    if (tid < EE) atomicAdd(&g_counts[tid], sh[tid]);
}

// ---------------- K2: warp-parallel exclusive scan ----------------
__global__ void k_scan() {
    int t = threadIdx.x;  // 32 threads
    int c  = (t < EE) ? g_counts[t] : 0;
    int tl = (c + M_TILE - 1) / M_TILE;
    int ic = c, it = tl;
    #pragma unroll
    for (int d = 1; d < 32; d <<= 1) {
        int vc = __shfl_up_sync(0xFFFFFFFFu, ic, d);
        int vt = __shfl_up_sync(0xFFFFFFFFu, it, d);
        if (t >= d) { ic += vc; it += vt; }
    }
    if (t < EE) {
        g_offsets[t] = ic - c;
        g_cursor[t]  = ic - c;
        g_tileOff[t] = it - tl;
    }
    int totC = __shfl_sync(0xFFFFFFFFu, ic, EE - 1);
    int totT = __shfl_sync(0xFFFFFFFFu, it, EE - 1);
    if (t == 0) {
        g_offsets[EE] = totC;
        g_tileOff[EE] = totT;
        g_numTiles = totT;
    }
}

// ---------------- K3: scatter rows into expert-grouped order ----------------
__global__ void k_scatter(const int* __restrict__ sid) {
    __shared__ int sHist[EE];
    __shared__ int sBase[EE];
    int tid = threadIdx.x;
    if (tid < EE) sHist[tid] = 0;
    __syncthreads();
    int gid = blockIdx.x * blockDim.x + tid;
    int e = -1, myIdx = 0;
    if (gid < NROWS) {
        e = sid[gid];
        myIdx = atomicAdd(&sHist[e], 1);
    }
    __syncthreads();
    if (tid < EE) sBase[tid] = atomicAdd(&g_cursor[tid], sHist[tid]);
    __syncthreads();
    if (gid < NROWS) g_perm[sBase[e] + myIdx] = gid;
}

// ---------------- K4: grouped expert MLP ----------------
#define XS_STRIDE 132
#define WT_STRIDE 132
#define SMEM_FLOATS (M_TILE * XS_STRIDE + HH * WT_STRIDE + HH + HH + 1)
#define SMEM_BYTES (SMEM_FLOATS * 4 + M_TILE * 4)

__device__ __forceinline__ void cp_async16(uint32_t dst_smem, const void* src) {
    asm volatile("cp.async.cg.shared.global [%0], [%1], 16;\n"
                 :: "r"(dst_smem), "l"(src));
}

__global__ __launch_bounds__(MAIN_THREADS, 2)
void k_main(const float* __restrict__ x,
            const float* __restrict__ W1,
            const float* __restrict__ b1,
            const float* __restrict__ W2,
            const float* __restrict__ b2,
            float* __restrict__ out)
{
    extern __shared__ float smem[];
    float* xs  = smem;                         // [128][132]
    float* wT  = smem + M_TILE * XS_STRIDE;    // [16][132] W1^T
    float* sb1 = wT + HH * WT_STRIDE;          // [16]
    float* sw2 = sb1 + HH;                     // [16]
    float* sb2 = sw2 + HH;                     // [1]
    int*  sRow = (int*)(sb2 + 1);              // [128]

    int t = blockIdx.x;
    if (t >= g_numTiles) return;

    int e = 0;
    #pragma unroll
    for (int i = 1; i < EE; i++)
        if (t >= g_tileOff[i]) e = i;
    int ti       = t - g_tileOff[e];
    int rowStart = g_offsets[e] + ti * M_TILE;
    int valid    = g_counts[e] - ti * M_TILE;
    if (valid > M_TILE) valid = M_TILE;

    int tid = threadIdx.x;

    // Stage row indices + expert weights/biases.
    if (tid < valid) sRow[tid] = g_perm[rowStart + tid];
    const float* W1e = W1 + (size_t)e * (DD * HH);
    #pragma unroll
    for (int m = 0; m < (DD * HH) / MAIN_THREADS; m++) {
        int i = tid + m * MAIN_THREADS;
        float v = W1e[i];
        wT[(i & 15) * WT_STRIDE + (i >> 4)] = v;   // transpose
    }
    if (tid < HH) {
        sb1[tid] = b1[e * HH + tid];
        sw2[tid] = W2[e * HH + tid];
    }
    if (tid == 0) sb2[0] = b2[e];
    __syncthreads();   // sRow visible before cp.async addressing

    // Stage x rows via cp.async: 32 16B copies in flight per thread.
    uint32_t xs_base = (uint32_t)__cvta_generic_to_shared(xs);
    if (valid == M_TILE) {
        #pragma unroll
        for (int m = 0; m < 32; m++) {
            int i = tid + m * MAIN_THREADS;
            int r = i >> 5, s = i & 31;
            const float* src = x + (size_t)sRow[r] * DD + s * 4;
            uint32_t dst = xs_base + (uint32_t)(r * XS_STRIDE + s * 4) * 4u;
            cp_async16(dst, src);
        }
    } else {
        for (int i = tid; i < valid * 32; i += MAIN_THREADS) {
            int r = i >> 5, s = i & 31;
            const float* src = x + (size_t)sRow[r] * DD + s * 4;
            uint32_t dst = xs_base + (uint32_t)(r * XS_STRIDE + s * 4) * 4u;
            cp_async16(dst, src);
        }
    }
    asm volatile("cp.async.commit_group;\ncp.async.wait_group 0;\n" ::: "memory");
    __syncthreads();

    if (tid < valid) {
        unsigned long long acc[HH];
        #pragma unroll
        for (int j = 0; j < HH; j++) acc[j] = 0ULL;   // {0.0f, 0.0f}

        uint32_t xaddr = xs_base + (uint32_t)(tid * XS_STRIDE) * 4u;
        uint32_t wbase = (uint32_t)__cvta_generic_to_shared(wT);

        #pragma unroll 8
        for (int k4 = 0; k4 < DD / 4; k4++) {
            unsigned long long x0, x1;
            asm("ld.shared.v2.b64 {%0, %1}, [%2];"
                : "=l"(x0), "=l"(x1) : "r"(xaddr + k4 * 16));
            #pragma unroll
            for (int j = 0; j < HH; j++) {
                unsigned long long w0, w1;
                asm("ld.shared.v2.b64 {%0, %1}, [%2];"
                    : "=l"(w0), "=l"(w1)
                    : "r"(wbase + (uint32_t)(j * WT_STRIDE * 4 + k4 * 16)));
                asm("fma.rn.f32x2 %0, %1, %2, %0;" : "+l"(acc[j]) : "l"(x0), "l"(w0));
                asm("fma.rn.f32x2 %0, %1, %2, %0;" : "+l"(acc[j]) : "l"(x1), "l"(w1));
            }
        }

        float y = sb2[0];
        #pragma unroll
        for (int j = 0; j < HH; j++) {
            float lo = __uint_as_float((uint32_t)acc[j]);
            float hi = __uint_as_float((uint32_t)(acc[j] >> 32));
            float h = fmaxf(lo + hi + sb1[j], 0.0f);
            y = fmaf(h, sw2[j], y);
        }
        out[sRow[tid]] = fmaxf(y, 0.0f);
    }
}

extern "C" void kernel_launch(void* const* d_in, const int* in_sizes, int n_in,
                              void* d_out, int out_size)
{
    const float* x   = (const float*)d_in[0];
    const int*   sid = (const int*)d_in[1];
    const float* W1  = (const float*)d_in[2];
    const float* b1  = (const float*)d_in[3];
    const float* W2  = (const float*)d_in[4];
    const float* b2  = (const float*)d_in[5];
    float* out = (float*)d_out;

    static bool attr_set = false;
    if (!attr_set) {
        cudaFuncSetAttribute(k_main, cudaFuncAttributeMaxDynamicSharedMemorySize, SMEM_BYTES);
        attr_set = true;
    }

    k_zero<<<1, 32>>>();
    k_hist<<<NROWS / 1024, 1024>>>(sid);
    k_scan<<<1, 32>>>();
    k_scatter<<<NROWS / 512, 512>>>(sid);
    k_main<<<MAX_TILES, MAIN_THREADS, SMEM_BYTES>>>(x, W1, b1, W2, b2, out);
}

// round 3
// speedup vs baseline: 2.7699x; 1.1607x over previous
#include <cuda_runtime.h>
#include <cuda_bf16.h>
#include <cstdint>

#define NROWS 262144
#define DD 128
#define HH 16
#define EE 21

#define M_TILE 256          // rows per tile (2 per thread)
#define KHALF 64            // floats per k-half
#define XSTRIDE 68          // padded row stride (floats), 16B-aligned, 4-way min conflicts
#define GRID_MAIN 148
#define THREADS_MAIN 128

// smem layout (floats)
#define XBUF_FLOATS (M_TILE * XSTRIDE)          // 17408
#define XBUF_BYTES  (XBUF_FLOATS * 4)           // 69632
#define WBUF_FLOATS (DD * HH)                   // 2048
#define SMEM_BYTES  (3 * XBUF_BYTES + 2 * WBUF_FLOATS * 4 + 2 * 40 * 4 + M_TILE * 4)

__device__ int g_counts[EE];
__device__ int g_cursor[EE];
__device__ int g_offsets[EE + 1];
__device__ int g_tileOff[EE + 1];
__device__ int g_numTiles;
__device__ int g_perm[NROWS];

// ---------------- K0: zero ----------------
__global__ void k_zero() {
    int t = threadIdx.x;
    if (t < EE) g_counts[t] = 0;
}

// ---------------- K1: histogram ----------------
__global__ void k_hist(const int* __restrict__ sid) {
    __shared__ int sh[EE];
    int tid = threadIdx.x;
    if (tid < EE) sh[tid] = 0;
    __syncthreads();
    int idx = blockIdx.x * blockDim.x + tid;
    if (idx < NROWS) atomicAdd(&sh[sid[idx]], 1);
    __syncthreads();
    if (tid < EE) atomicAdd(&g_counts[tid], sh[tid]);
}

// ---------------- K2: warp scan ----------------
__global__ void k_scan() {
    int t = threadIdx.x;
    int c  = (t < EE) ? g_counts[t] : 0;
    int tl = (c + M_TILE - 1) / M_TILE;
    int ic = c, it = tl;
    #pragma unroll
    for (int d = 1; d < 32; d <<= 1) {
        int vc = __shfl_up_sync(0xFFFFFFFFu, ic, d);
        int vt = __shfl_up_sync(0xFFFFFFFFu, it, d);
        if (t >= d) { ic += vc; it += vt; }
    }
    if (t < EE) {
        g_offsets[t] = ic - c;
        g_cursor[t]  = ic - c;
        g_tileOff[t] = it - tl;
    }
    int totC = __shfl_sync(0xFFFFFFFFu, ic, EE - 1);
    int totT = __shfl_sync(0xFFFFFFFFu, it, EE - 1);
    if (t == 0) {
        g_offsets[EE] = totC;
        g_tileOff[EE] = totT;
        g_numTiles = totT;
    }
}

// ---------------- K3: scatter ----------------
__global__ void k_scatter(const int* __restrict__ sid) {
    __shared__ int sHist[EE];
    __shared__ int sBase[EE];
    int tid = threadIdx.x;
    if (tid < EE) sHist[tid] = 0;
    __syncthreads();
    int gid = blockIdx.x * blockDim.x + tid;
    int e = -1, myIdx = 0;
    if (gid < NROWS) {
        e = sid[gid];
        myIdx = atomicAdd(&sHist[e], 1);
    }
    __syncthreads();
    if (tid < EE) sBase[tid] = atomicAdd(&g_cursor[tid], sHist[tid]);
    __syncthreads();
    if (gid < NROWS) g_perm[sBase[e] + myIdx] = gid;
}

// ---------------- K4: persistent pipelined expert MLP ----------------
__device__ __forceinline__ void cp_async16(uint32_t dst, const void* src) {
    asm volatile("cp.async.cg.shared.global [%0], [%1], 16;\n" :: "r"(dst), "l"(src));
}
__device__ __forceinline__ void cp_async4(uint32_t dst, const void* src) {
    asm volatile("cp.async.ca.shared.global [%0], [%1], 4;\n" :: "r"(dst), "l"(src));
}
#define CP_COMMIT() asm volatile("cp.async.commit_group;" ::: "memory")
#define CP_WAIT2()  asm volatile("cp.async.wait_group 2;" ::: "memory")

#define FMA2(acc, a, b) asm("fma.rn.f32x2 %0, %1, %2, %0;" : "+l"(acc) : "l"(a), "l"(b))

// Process one scalar d: 2 rows (afl, bfl), 16 h outputs via 4 broadcast LDS.128.
#define DSTEP(afl, bfl, waddr)                                                     \
    do {                                                                           \
        unsigned long long _xa, _xb, _w0, _w1;                                     \
        asm("mov.b64 %0, {%1,%1};" : "=l"(_xa) : "f"(afl));                        \
        asm("mov.b64 %0, {%1,%1};" : "=l"(_xb) : "f"(bfl));                        \
        asm("ld.shared.v2.b64 {%0,%1}, [%2];" : "=l"(_w0), "=l"(_w1) : "r"(waddr));\
        FMA2(accA[0], _xa, _w0); FMA2(accA[1], _xa, _w1);                          \
        FMA2(accB[0], _xb, _w0); FMA2(accB[1], _xb, _w1);                          \
        asm("ld.shared.v2.b64 {%0,%1}, [%2];" : "=l"(_w0), "=l"(_w1) : "r"((waddr) + 16)); \
        FMA2(accA[2], _xa, _w0); FMA2(accA[3], _xa, _w1);                          \
        FMA2(accB[2], _xb, _w0); FMA2(accB[3], _xb, _w1);                          \
        asm("ld.shared.v2.b64 {%0,%1}, [%2];" : "=l"(_w0), "=l"(_w1) : "r"((waddr) + 32)); \
        FMA2(accA[4], _xa, _w0); FMA2(accA[5], _xa, _w1);                          \
        FMA2(accB[4], _xb, _w0); FMA2(accB[5], _xb, _w1);                          \
        asm("ld.shared.v2.b64 {%0,%1}, [%2];" : "=l"(_w0), "=l"(_w1) : "r"((waddr) + 48)); \
        FMA2(accA[6], _xa, _w0); FMA2(accA[7], _xa, _w1);                          \
        FMA2(accB[6], _xb, _w0); FMA2(accB[7], _xb, _w1);                          \
    } while (0)

__global__ __launch_bounds__(THREADS_MAIN, 1)
void k_main(const float* __restrict__ x,
            const float* __restrict__ W1,
            const float* __restrict__ b1,
            const float* __restrict__ W2,
            const float* __restrict__ b2,
            float* __restrict__ out)
{
    extern __shared__ float smem[];
    float* xs = smem;                               // 3 x-buffers
    float* wb = xs + 3 * XBUF_FLOATS;               // 2 weight buffers [128][16]
    float* wx = wb + 2 * WBUF_FLOATS;               // 2 x 40: b1[16], w2[16], b2
    int*  sRow = (int*)(wx + 2 * 40);               // 256 row indices (next tile)

    int nT = g_numTiles;
    int q = (nT + GRID_MAIN - 1) / GRID_MAIN;
    int t0 = blockIdx.x * q;
    int t1 = t0 + q; if (t1 > nT) t1 = nT;
    if (t0 >= t1) return;

    int tid = threadIdx.x;
    uint32_t xs_sh = (uint32_t)__cvta_generic_to_shared(xs);
    uint32_t wb_sh = (uint32_t)__cvta_generic_to_shared(wb);
    uint32_t wx_sh = (uint32_t)__cvta_generic_to_shared(wx);

    // stage one k-half of the (already-published) sRow tile into buffer `buf`
    auto stage_x = [&](int kh, int buf) {
        uint32_t dstBase = xs_sh + (uint32_t)buf * XBUF_BYTES;
        #pragma unroll
        for (int m = 0; m < 32; m++) {
            int idx = tid + m * THREADS_MAIN;
            int r = idx >> 4, s = idx & 15;
            int row = sRow[r];
            const float* src = x + (size_t)row * DD + kh * KHALF + s * 4;
            cp_async16(dstBase + (uint32_t)(r * XSTRIDE + s * 4) * 4u, src);
        }
    };
    auto stage_w = [&](int e, int par) {
        const float* W1e = W1 + (size_t)e * WBUF_FLOATS;
        uint32_t dst = wb_sh + (uint32_t)par * (WBUF_FLOATS * 4);
        #pragma unroll
        for (int m = 0; m < 4; m++) {
            int s = tid + m * THREADS_MAIN;
            cp_async16(dst + (uint32_t)s * 16u, W1e + s * 4);
        }
        uint32_t xdst = wx_sh + (uint32_t)par * 160u;
        if (tid < 4)       cp_async16(xdst + tid * 16u, b1 + e * HH + tid * 4);
        else if (tid < 8)  cp_async16(xdst + 64u + (tid - 4) * 16u, W2 + e * HH + (tid - 4) * 4);
        else if (tid == 8) cp_async4(xdst + 128u, b2 + e);
    };
    auto tile_meta = [&](int t, int& e, int& rs, int& v) {
        e = 0;
        #pragma unroll
        for (int j = 1; j < EE; j++)
            if (t >= g_tileOff[j]) e = j;
        int ti = t - g_tileOff[e];
        rs = g_offsets[e] + ti * M_TILE;
        v = g_counts[e] - ti * M_TILE;
        if (v > M_TILE) v = M_TILE;
    };

    unsigned long long accA[8], accB[8];
    auto compute_half = [&](int kh, int buf, int par) {
        uint32_t xA = xs_sh + (uint32_t)buf * XBUF_BYTES + (uint32_t)(tid * XSTRIDE) * 4u;
        uint32_t xB = xA + (uint32_t)(128 * XSTRIDE) * 4u;
        uint32_t wB = wb_sh + (uint32_t)par * (WBUF_FLOATS * 4) + (uint32_t)kh * (KHALF * HH * 4);
        #pragma unroll 4
        for (int d4 = 0; d4 < 16; d4++) {
            float a0, a1, a2, a3, c0, c1, c2, c3;
            asm("ld.shared.v4.f32 {%0,%1,%2,%3}, [%4];"
                : "=f"(a0), "=f"(a1), "=f"(a2), "=f"(a3) : "r"(xA + d4 * 16));
            asm("ld.shared.v4.f32 {%0,%1,%2,%3}, [%4];"
                : "=f"(c0), "=f"(c1), "=f"(c2), "=f"(c3) : "r"(xB + d4 * 16));
            uint32_t wd = wB + (uint32_t)(d4 * 4) * 64u;
            DSTEP(a0, c0, wd);
            DSTEP(a1, c1, wd + 64);
            DSTEP(a2, c2, wd + 128);
            DSTEP(a3, c3, wd + 192);
        }
    };

    // ---- prologue: tile t0 ----
    int eCur, rsCur, vCur;
    tile_meta(t0, eCur, rsCur, vCur);
    int rCurA = g_perm[rsCur + (tid < vCur ? tid : 0)];
    int rCurB = g_perm[rsCur + (tid + 128 < vCur ? tid + 128 : 0)];
    sRow[tid] = rCurA;
    sRow[tid + 128] = rCurB;
    __syncthreads();

    int eW0 = -1, eW1 = -1;
    {   // group 0: (t0, kh0) + weights parity t0&1
        int par = t0 & 1;
        stage_w(eCur, par);
        if (par) eW1 = eCur; else eW0 = eCur;
        stage_x(0, 0);
        CP_COMMIT();
        stage_x(1, 1);        // group 1: (t0, kh1)
        CP_COMMIT();
    }

    int eNxt = 0, rsNxt = 0, vNxt = 0, rNxtA = 0, rNxtB = 0;

    for (int i = t0; i < t1; i++) {
        int f0 = 2 * (i - t0);
        bool hasNext = (i + 1 < t1);
        int parCur = i & 1;

        // ---- phase kh0 ----
        if (hasNext) {
            tile_meta(i + 1, eNxt, rsNxt, vNxt);
            rNxtA = g_perm[rsNxt + (tid < vNxt ? tid : 0)];
            rNxtB = g_perm[rsNxt + (tid + 128 < vNxt ? tid + 128 : 0)];
        }
        __syncthreads();                              // prev compute done; sRow free
        if (hasNext) { sRow[tid] = rNxtA; sRow[tid + 128] = rNxtB; }
        __syncthreads();                              // sRow visible
        if (hasNext) {
            int parN = (i + 1) & 1;
            int eOld = parN ? eW1 : eW0;
            if (eNxt != eOld) {
                stage_w(eNxt, parN);
                if (parN) eW1 = eNxt; else eW0 = eNxt;
            }
            stage_x(0, (f0 + 2) % 3);
        }
        CP_COMMIT();
        CP_WAIT2();                                   // group f0 complete
        __syncthreads();                              // all threads' copies visible
        #pragma unroll
        for (int j = 0; j < 8; j++) { accA[j] = 0ULL; accB[j] = 0ULL; }
        compute_half(0, f0 % 3, parCur);

        // ---- phase kh1 ----
        __syncthreads();                              // kh0 compute done (buf (f0)%3... reuse safe)
        if (hasNext) stage_x(1, (f0 + 3) % 3);
        CP_COMMIT();
        CP_WAIT2();                                   // group f0+1 complete
        __syncthreads();
        compute_half(1, (f0 + 1) % 3, parCur);

        // ---- epilogue ----
        {
            const float* wxp = wx + parCur * 40;
            float yA = wxp[32], yB = wxp[32];
            #pragma unroll
            for (int p = 0; p < 8; p++) {
                float b1l = wxp[2 * p], b1h = wxp[2 * p + 1];
                float w2l = wxp[16 + 2 * p], w2h = wxp[16 + 2 * p + 1];
                float al = __uint_as_float((uint32_t)accA[p]);
                float ah = __uint_as_float((uint32_t)(accA[p] >> 32));
                float bl = __uint_as_float((uint32_t)accB[p]);
                float bh = __uint_as_float((uint32_t)(accB[p] >> 32));
                yA = fmaf(fmaxf(al + b1l, 0.0f), w2l, yA);
                yA = fmaf(fmaxf(ah + b1h, 0.0f), w2h, yA);
                yB = fmaf(fmaxf(bl + b1l, 0.0f), w2l, yB);
                yB = fmaf(fmaxf(bh + b1h, 0.0f), w2h, yB);
            }
            if (tid < vCur)       out[rCurA] = fmaxf(yA, 0.0f);
            if (tid + 128 < vCur) out[rCurB] = fmaxf(yB, 0.0f);
        }

        eCur = eNxt; rsCur = rsNxt; vCur = vNxt;
        rCurA = rNxtA; rCurB = rNxtB;
    }
}

extern "C" void kernel_launch(void* const* d_in, const int* in_sizes, int n_in,
                              void* d_out, int out_size)
{
    const float* x   = (const float*)d_in[0];
    const int*   sid = (const int*)d_in[1];
    const float* W1  = (const float*)d_in[2];
    const float* b1  = (const float*)d_in[3];
    const float* W2  = (const float*)d_in[4];
    const float* b2  = (const float*)d_in[5];
    float* out = (float*)d_out;

    static bool attr_set = false;
    if (!attr_set) {
        cudaFuncSetAttribute(k_main, cudaFuncAttributeMaxDynamicSharedMemorySize, SMEM_BYTES);
        attr_set = true;
    }

    k_zero<<<1, 32>>>();
    k_hist<<<NROWS / 1024, 1024>>>(sid);
    k_scan<<<1, 32>>>();
    k_scatter<<<NROWS / 1024, 1024>>>(sid);
    k_main<<<GRID_MAIN, THREADS_MAIN, SMEM_BYTES>>>(x, W1, b1, W2, b2, out);
}

// round 4
// speedup vs baseline: 2.9489x; 1.0646x over previous
#include <cuda_runtime.h>
#include <cuda_bf16.h>
#include <cstdint>

#define NROWS 262144
#define DD 128
#define HH 16
#define EE 21

#define THREADS 128
#define RPT 8                    // rows per thread
#define M_TILE 1024              // THREADS * RPT
#define CHUNK_D 16               // d per phase
#define NPHASE 8                 // 128 / 16
#define GRID_MAIN 148

#define XBUF_BYTES (M_TILE * CHUNK_D * 4)     // 65536
#define WB_FLOATS (DD * HH)                   // 2048
#define WB_BYTES (WB_FLOATS * 4)              // 8192
#define SMEM_BYTES (3 * XBUF_BYTES + 2 * WB_BYTES + 2 * 160 + 2 * M_TILE * 4)

__device__ int g_counts[EE];
__device__ int g_cursor[EE];
__device__ int g_offsets[EE + 1];
__device__ int g_tileOff[EE + 1];
__device__ int g_numTiles;
__device__ int g_perm[NROWS];

// ---------------- K1: histogram (int4 vectorized) ----------------
__global__ void k_hist(const int* __restrict__ sid) {
    __shared__ int sh[EE];
    int tid = threadIdx.x;
    if (tid < EE) sh[tid] = 0;
    __syncthreads();
    int4 v = ((const int4*)sid)[blockIdx.x * blockDim.x + tid];
    atomicAdd(&sh[v.x], 1);
    atomicAdd(&sh[v.y], 1);
    atomicAdd(&sh[v.z], 1);
    atomicAdd(&sh[v.w], 1);
    __syncthreads();
    if (tid < EE) atomicAdd(&g_counts[tid], sh[tid]);
}

// ---------------- K2: warp scan (+ zero counts for next replay) ----------
__global__ void k_scan() {
    int t = threadIdx.x;
    int c  = (t < EE) ? g_counts[t] : 0;
    int tl = (c + M_TILE - 1) / M_TILE;
    int ic = c, it = tl;
    #pragma unroll
    for (int d = 1; d < 32; d <<= 1) {
        int vc = __shfl_up_sync(0xFFFFFFFFu, ic, d);
        int vt = __shfl_up_sync(0xFFFFFFFFu, it, d);
        if (t >= d) { ic += vc; it += vt; }
    }
    if (t < EE) {
        g_offsets[t] = ic - c;
        g_cursor[t]  = ic - c;
        g_tileOff[t] = it - tl;
        g_counts[t]  = 0;              // reset for next graph replay
    }
    int totC = __shfl_sync(0xFFFFFFFFu, ic, EE - 1);
    int totT = __shfl_sync(0xFFFFFFFFu, it, EE - 1);
    if (t == 0) {
        g_offsets[EE] = totC;
        g_tileOff[EE] = totT;
        g_numTiles = totT;
    }
}

// ---------------- K3: scatter ----------------
__global__ void k_scatter(const int* __restrict__ sid) {
    __shared__ int sHist[EE];
    __shared__ int sBase[EE];
    int tid = threadIdx.x;
    if (tid < EE) sHist[tid] = 0;
    __syncthreads();
    int gid = blockIdx.x * blockDim.x + tid;
    int e = sid[gid];
    int myIdx = atomicAdd(&sHist[e], 1);
    __syncthreads();
    if (tid < EE) sBase[tid] = atomicAdd(&g_cursor[tid], sHist[tid]);
    __syncthreads();
    g_perm[sBase[e] + myIdx] = gid;
}

// ---------------- K4: persistent pipelined expert MLP ----------------
__device__ __forceinline__ void cp_async16(uint32_t dst, const void* src) {
    asm volatile("cp.async.cg.shared.global [%0], [%1], 16;\n" :: "r"(dst), "l"(src));
}
__device__ __forceinline__ void cp_async4(uint32_t dst, const void* src) {
    asm volatile("cp.async.ca.shared.global [%0], [%1], 4;\n" :: "r"(dst), "l"(src));
}
#define CP_COMMIT() asm volatile("cp.async.commit_group;" ::: "memory")
#define CP_WAIT1()  asm volatile("cp.async.wait_group 1;" ::: "memory")
#define FMA2(acc, a, b) asm("fma.rn.f32x2 %0, %1, %2, %0;" : "+l"(acc) : "l"(a), "l"(b))

__device__ __forceinline__ unsigned long long bcast2(float f) {
    unsigned long long r;
    asm("mov.b64 %0, {%1,%1};" : "=l"(r) : "f"(f));
    return r;
}

__global__ __launch_bounds__(THREADS, 1)
void k_main(const float* __restrict__ x,
            const float* __restrict__ W1,
            const float* __restrict__ b1,
            const float* __restrict__ W2,
            const float* __restrict__ b2,
            float* __restrict__ out)
{
    extern __shared__ float smem[];
    float* xs = smem;                                    // 3 x 64KB chunk buffers
    float* wb = xs + 3 * (XBUF_BYTES / 4);               // 2 x [128][16]
    float* wx = wb + 2 * WB_FLOATS;                      // 2 x 40 (b1,w2,b2)
    int* sRow = (int*)(wx + 2 * 40);                     // 2 x 1024

    int nT = g_numTiles;
    int q = (nT + GRID_MAIN - 1) / GRID_MAIN;
    int t0 = blockIdx.x * q;
    int t1 = t0 + q; if (t1 > nT) t1 = nT;
    if (t0 >= t1) return;

    int tid = threadIdx.x;
    uint32_t xs_sh = (uint32_t)__cvta_generic_to_shared(xs);
    uint32_t wb_sh = (uint32_t)__cvta_generic_to_shared(wb);
    uint32_t wx_sh = (uint32_t)__cvta_generic_to_shared(wx);

    auto tile_meta = [&](int t, int& e, int& rs, int& v) {
        e = 0;
        #pragma unroll
        for (int j = 1; j < EE; j++)
            if (t >= g_tileOff[j]) e = j;
        int ti = t - g_tileOff[e];
        rs = g_offsets[e] + ti * M_TILE;
        v = g_offsets[e + 1] - rs;
        if (v > M_TILE) v = M_TILE;
    };
    auto stage_w = [&](int e, int par) {
        const float* W1e = W1 + (size_t)e * WB_FLOATS;
        uint32_t dst = wb_sh + (uint32_t)par * WB_BYTES;
        #pragma unroll
        for (int m = 0; m < 4; m++) {
            int s = tid + m * THREADS;
            cp_async16(dst + (uint32_t)s * 16u, W1e + s * 4);
        }
        uint32_t xdst = wx_sh + (uint32_t)par * 160u;
        if (tid < 4)       cp_async16(xdst + tid * 16u, b1 + e * HH + tid * 4);
        else if (tid < 8)  cp_async16(xdst + 64u + (tid - 4) * 16u, W2 + e * HH + (tid - 4) * 4);
        else if (tid == 8) cp_async4(xdst + 128u, b2 + e);
    };
    // stage k-chunk c2 (16 d) of the tile whose rows are in sRow[p2] into buffer buf
    auto stage_x = [&](int c2, int p2, int buf) {
        const int* rp = sRow + p2 * M_TILE;
        uint32_t bb = xs_sh + (uint32_t)buf * XBUF_BYTES;
        const float* xc = x + c2 * CHUNK_D;
        #pragma unroll
        for (int m = 0; m < 32; m++) {
            int idx = tid + m * THREADS;
            int r = idx >> 2, s = idx & 3;
            int row = rp[r];
            uint32_t dst = bb + (uint32_t)(r * 64) + (uint32_t)(((s + (r >> 1)) & 3) << 4);
            cp_async16(dst, xc + (size_t)row * DD + s * 4);
        }
    };

    // per-thread row offsets within the tile (constant)
    uint32_t roff[RPT];
    int pk[RPT];
    #pragma unroll
    for (int k = 0; k < RPT; k++) {
        int r = tid + k * THREADS;
        roff[k] = (uint32_t)r * 64u;
        pk[k] = (r >> 1) & 3;
    }

    // ---- prologue ----
    int eC, rsC, vC;
    tile_meta(t0, eC, rsC, vC);
    #pragma unroll
    for (int k = 0; k < RPT; k++) {
        int r = tid + k * THREADS;
        int idx = (r < vC) ? r : 0;
        sRow[(t0 & 1) * M_TILE + r] = g_perm[rsC + idx];
    }
    __syncthreads();
    int eW0 = -1, eW1 = -1;
    {
        int par0 = t0 & 1;
        stage_w(eC, par0);
        if (par0) eW1 = eC; else eW0 = eC;
        stage_x(0, par0, 0);
        CP_COMMIT();
        stage_x(1, par0, 1);
        CP_COMMIT();
    }

    unsigned long long acc[RPT][8];
    int eN = eC, rsN = 0, vN = vC;
    int rrN[RPT];

    int nChunk = (t1 - t0) * NPHASE;
    for (int j = 0; j < nChunk; j++) {
        int i = t0 + (j >> 3);
        int c = j & 7;
        int par = i & 1;

        // prefetch next tile meta + perm rows early in the tile
        if (c == 0 && (i + 1) < t1) {
            tile_meta(i + 1, eN, rsN, vN);
            #pragma unroll
            for (int k = 0; k < RPT; k++) {
                int r = tid + k * THREADS;
                int idx = (r < vN) ? r : 0;
                rrN[k] = g_perm[rsN + idx];
            }
        }

        CP_WAIT1();
        __syncthreads();

        if (c == 1 && (i + 1) < t1) {
            #pragma unroll
            for (int k = 0; k < RPT; k++)
                sRow[((i + 1) & 1) * M_TILE + tid + k * THREADS] = rrN[k];
        }

        int j2 = j + 2;
        if (j2 < nChunk) {
            int c2 = j2 & 7;
            bool nextTile = (j2 >> 3) != (j >> 3);
            int p2 = nextTile ? (par ^ 1) : par;
            if (nextTile && c2 == 0) {
                int eOld = p2 ? eW1 : eW0;
                if (eN != eOld) {
                    stage_w(eN, p2);
                    if (p2) eW1 = eN; else eW0 = eN;
                }
            }
            stage_x(c2, p2, j2 % 3);
        }
        CP_COMMIT();

        if (c == 0) {
            #pragma unroll
            for (int k = 0; k < RPT; k++)
                #pragma unroll
                for (int p = 0; p < 8; p++) acc[k][p] = 0ULL;
        }

        // ---- compute this 16-d chunk ----
        {
            uint32_t xb = xs_sh + (uint32_t)(j % 3) * XBUF_BYTES;
            uint32_t wd = wb_sh + (uint32_t)par * WB_BYTES + (uint32_t)(c * CHUNK_D * 64);
            #pragma unroll
            for (int g = 0; g < 4; g++) {
                float4 xv[RPT];
                #pragma unroll
                for (int k = 0; k < RPT; k++) {
                    uint32_t a = xb + roff[k] + (uint32_t)(((g + pk[k]) & 3) << 4);
                    asm("ld.shared.v4.f32 {%0,%1,%2,%3}, [%4];"
                        : "=f"(xv[k].x), "=f"(xv[k].y), "=f"(xv[k].z), "=f"(xv[k].w)
                        : "r"(a));
                }
                #pragma unroll
                for (int dd = 0; dd < 4; dd++) {
                    unsigned long long w[8];
                    uint32_t wa = wd + (uint32_t)((g * 4 + dd) * 64);
                    asm("ld.shared.v2.b64 {%0,%1}, [%2];" : "=l"(w[0]), "=l"(w[1]) : "r"(wa));
                    asm("ld.shared.v2.b64 {%0,%1}, [%2];" : "=l"(w[2]), "=l"(w[3]) : "r"(wa + 16));
                    asm("ld.shared.v2.b64 {%0,%1}, [%2];" : "=l"(w[4]), "=l"(w[5]) : "r"(wa + 32));
                    asm("ld.shared.v2.b64 {%0,%1}, [%2];" : "=l"(w[6]), "=l"(w[7]) : "r"(wa + 48));
                    #pragma unroll
                    for (int k = 0; k < RPT; k++) {
                        float xf = (dd == 0) ? xv[k].x : (dd == 1) ? xv[k].y
                                 : (dd == 2) ? xv[k].z : xv[k].w;
                        unsigned long long xd = bcast2(xf);
                        FMA2(acc[k][0], xd, w[0]);
                        FMA2(acc[k][1], xd, w[1]);
                        FMA2(acc[k][2], xd, w[2]);
                        FMA2(acc[k][3], xd, w[3]);
                        FMA2(acc[k][4], xd, w[4]);
                        FMA2(acc[k][5], xd, w[5]);
                        FMA2(acc[k][6], xd, w[6]);
                        FMA2(acc[k][7], xd, w[7]);
                    }
                }
            }
        }

        // ---- tile epilogue ----
        if (c == 7) {
            const float* wxp = wx + par * 40;
            float b1r[HH], w2r[HH];
            #pragma unroll
            for (int h = 0; h < HH; h++) { b1r[h] = wxp[h]; w2r[h] = wxp[16 + h]; }
            float b2v = wxp[32];
            const int* rp = sRow + par * M_TILE;
            #pragma unroll
            for (int k = 0; k < RPT; k++) {
                int r = tid + k * THREADS;
                float y = b2v;
                #pragma unroll
                for (int p = 0; p < 8; p++) {
                    float lo = __uint_as_float((uint32_t)acc[k][p]);
                    float hi = __uint_as_float((uint32_t)(acc[k][p] >> 32));
                    y = fmaf(fmaxf(lo + b1r[2 * p], 0.0f), w2r[2 * p], y);
                    y = fmaf(fmaxf(hi + b1r[2 * p + 1], 0.0f), w2r[2 * p + 1], y);
                }
                if (r < vC) out[rp[r]] = fmaxf(y, 0.0f);
            }
            eC = eN; vC = vN;
        }
    }
}

extern "C" void kernel_launch(void* const* d_in, const int* in_sizes, int n_in,
                              void* d_out, int out_size)
{
    const float* x   = (const float*)d_in[0];
    const int*   sid = (const int*)d_in[1];
    const float* W1  = (const float*)d_in[2];
    const float* b1  = (const float*)d_in[3];
    const float* W2  = (const float*)d_in[4];
    const float* b2  = (const float*)d_in[5];
    float* out = (float*)d_out;

    static bool attr_set = false;
    if (!attr_set) {
        cudaFuncSetAttribute(k_main, cudaFuncAttributeMaxDynamicSharedMemorySize, SMEM_BYTES);
        attr_set = true;
    }

    k_hist<<<NROWS / 4096, 1024>>>(sid);
    k_scan<<<1, 32>>>();
    k_scatter<<<NROWS / 1024, 1024>>>(sid);
    k_main<<<GRID_MAIN, THREADS, SMEM_BYTES>>>(x, W1, b1, W2, b2, out);
}